// round 2
// baseline (speedup 1.0000x reference)
#include <cuda_runtime.h>
#include <math.h>

// ---------------- problem constants ----------------
#define NE   32          // experts
#define TOPK 8
#define HD   2048        // hidden
#define ID   1024        // intermediate
#define AMAX 2
#define RR   16          // lora rank
#define NT   4096        // tokens
#define TE   (NT*TOPK)   // expanded tokens = 32768
#define MAXTILES 320     // >= sum ceil(cnt_e/128) (bounded by 287)

// ---------------- device scratch (static, no allocs) ----------------
__device__ int   g_cnt[NE];
__device__ int   g_off[NE+1];
__device__ int   g_tok[TE];     // source token per sorted position
__device__ int   g_adp[TE];     // adapter per sorted position
__device__ int   g_pos[TE];     // sorted position of expanded index i
__device__ int   g_tile_e[MAXTILES];
__device__ int   g_tile_m[MAXTILES];
__device__ int   g_ntiles;
__device__ float g_Z[(size_t)TE*RR];
__device__ float g_G[(size_t)TE*ID];   // gate, then h after silu
__device__ float g_U[(size_t)TE*ID];   // up
__device__ float g_O[(size_t)TE*HD];   // down output (sorted order)

// ---------------- helpers ----------------
__device__ __forceinline__ float to_tf32(float x) {
    unsigned u;
    asm("cvt.rna.tf32.f32 %0, %1;" : "=r"(u) : "f"(x));
    return __uint_as_float(u);
}

__device__ __forceinline__ void mma_tf32(float* c, const unsigned* a, const unsigned* b) {
    asm volatile(
        "mma.sync.aligned.m16n8k8.row.col.f32.tf32.tf32.f32 "
        "{%0,%1,%2,%3}, {%4,%5,%6,%7}, {%8,%9}, {%0,%1,%2,%3};\n"
        : "+f"(c[0]), "+f"(c[1]), "+f"(c[2]), "+f"(c[3])
        : "r"(a[0]), "r"(a[1]), "r"(a[2]), "r"(a[3]),
          "r"(b[0]), "r"(b[1]));
}

// ---------------- routing: count, scan, scatter, tile list ----------------
__global__ void routing_kernel(const int* __restrict__ sel, const int* __restrict__ adp) {
    __shared__ int s_cnt[NE];
    __shared__ int s_cur[NE];
    const int tid = threadIdx.x;
    if (tid < NE) s_cnt[tid] = 0;
    __syncthreads();
    for (int i = tid; i < TE; i += blockDim.x)
        atomicAdd(&s_cnt[sel[i]], 1);
    __syncthreads();
    if (tid == 0) {
        int acc = 0, idx = 0;
        for (int e = 0; e < NE; e++) {
            int c = s_cnt[e];
            g_cnt[e] = c;
            g_off[e] = acc;
            s_cur[e] = acc;
            acc += c;
            int mt = (c + 127) >> 7;
            for (int i = 0; i < mt; i++) { g_tile_e[idx] = e; g_tile_m[idx] = i; idx++; }
        }
        g_off[NE] = acc;
        g_ntiles = idx;
    }
    __syncthreads();
    for (int i = tid; i < TE; i += blockDim.x) {
        int e = sel[i];
        int pos = atomicAdd(&s_cur[e], 1);
        int t = i >> 3;  // TOPK = 8
        g_tok[pos] = t;
        g_adp[pos] = adp[t];
        g_pos[i]   = pos;
    }
}

// ---------------- LoRA A projection: Z[p,0..15] = x_p @ A[a_p, e_p] ----------------
// proj: 0/1 -> X = hidden (gathered rows, K=HD), 2 -> X = g_G (h, direct rows, K=ID)
__global__ __launch_bounds__(256)
void z_kernel(const float* __restrict__ hidden,
              const float* __restrict__ Abase,
              int proj, int K)
{
    if ((int)blockIdx.y >= g_ntiles) return;
    const int e   = g_tile_e[blockIdx.y];
    const int m0  = g_tile_m[blockIdx.y] << 7;
    const int cnt = g_cnt[e];
    const int off = g_off[e];

    const int tid = threadIdx.x;
    const int r   = tid >> 1;          // 0..127
    const int jb  = (tid & 1) * 8;     // j half
    const int gm  = m0 + r;
    const bool valid = gm < cnt;
    const int p = off + (valid ? gm : (cnt - 1));

    const float* xrow = (proj < 2) ? (hidden + (size_t)g_tok[p] * HD)
                                   : (g_G + (size_t)p * ID);
    const int a = g_adp[p];

    float z[8] = {0.f,0.f,0.f,0.f,0.f,0.f,0.f,0.f};

    __shared__ float As[2][64][20];   // pad 20: 16B-aligned rows, low conflicts

    for (int kt = 0; kt < K; kt += 64) {
        // load both adapters' A tile: 2*64*16 floats = 512 float4
        for (int u = tid; u < 512; u += 256) {
            int aa = u >> 8, rem = u & 255;
            int kk = rem >> 2, j4 = (rem & 3) << 2;
            float4 v = *(const float4*)(Abase + (((size_t)aa*NE + e)*K + kt + kk)*RR + j4);
            *(float4*)&As[aa][kk][j4] = v;
        }
        __syncthreads();
        #pragma unroll 4
        for (int kk = 0; kk < 64; kk++) {
            float xv = __ldg(xrow + kt + kk);
            float4 za = *(const float4*)&As[a][kk][jb];
            float4 zb = *(const float4*)&As[a][kk][jb + 4];
            z[0] += xv * za.x; z[1] += xv * za.y; z[2] += xv * za.z; z[3] += xv * za.w;
            z[4] += xv * zb.x; z[5] += xv * zb.y; z[6] += xv * zb.z; z[7] += xv * zb.w;
        }
        __syncthreads();
    }
    if (valid) {
        #pragma unroll
        for (int jj = 0; jj < 8; jj++)
            g_Z[(size_t)p*RR + jb + jj] = z[jj];
    }
}

// ---------------- grouped GEMM (tf32 mma) + LoRA-B epilogue ----------------
struct SmemMain { float Xs[128][36]; float Ws[32][136]; };
struct SmemEpi  { float Zs[128][16]; float Bs[2][16][128]; };
union SmemU { SmemMain m; SmemEpi e; };

// proj: 0 gate (X=hidden gather, out=g_G), 1 up (out=g_U), 2 down (X=g_G, out=g_O)
__global__ __launch_bounds__(256)
void gemm_kernel(const float* __restrict__ hidden,
                 const float* __restrict__ Wbase,
                 const float* __restrict__ Bbase,
                 int proj, int K, int N)
{
    if ((int)blockIdx.y >= g_ntiles) return;
    const int e   = g_tile_e[blockIdx.y];
    const int m0  = g_tile_m[blockIdx.y] << 7;
    const int cnt = g_cnt[e];
    const int off = g_off[e];
    const int n0  = blockIdx.x * 128;

    const int tid  = threadIdx.x;
    const int lane = tid & 31;
    const int wid  = tid >> 5;
    const int row_base = (wid & 1) * 64;   // 2 warps in M, 64 rows each
    const int col_base = (wid >> 1) * 32;  // 4 warps in N, 32 cols each

    __shared__ SmemU sm;
    __shared__ int s_src[128];
    __shared__ int s_adp[128];

    const float* Xbase; int ldx; int gather; float* Out;
    if (proj == 0)      { Xbase = hidden; ldx = HD; gather = 1; Out = g_G; }
    else if (proj == 1) { Xbase = hidden; ldx = HD; gather = 1; Out = g_U; }
    else                { Xbase = g_G;    ldx = ID; gather = 0; Out = g_O; }

    for (int r = tid; r < 128; r += 256) {
        int gm = m0 + r;
        int p  = off + (gm < cnt ? gm : (cnt - 1));
        s_src[r] = gather ? g_tok[p] : p;
        s_adp[r] = g_adp[p];
    }

    float c[4][4][4];
    #pragma unroll
    for (int i = 0; i < 4; i++)
        #pragma unroll
        for (int j = 0; j < 4; j++)
            #pragma unroll
            for (int k = 0; k < 4; k++) c[i][j][k] = 0.f;

    const float* Wexp = Wbase + (size_t)e * K * N;

    __syncthreads();

    for (int kt = 0; kt < K; kt += 32) {
        // X tile: 128 rows x 32 cols = 1024 float4
        #pragma unroll
        for (int u4 = tid; u4 < 1024; u4 += 256) {
            int r = u4 >> 3, c4 = (u4 & 7) << 2;
            const float4 v = *(const float4*)(Xbase + (size_t)s_src[r]*ldx + kt + c4);
            sm.m.Xs[r][c4+0] = to_tf32(v.x);
            sm.m.Xs[r][c4+1] = to_tf32(v.y);
            sm.m.Xs[r][c4+2] = to_tf32(v.z);
            sm.m.Xs[r][c4+3] = to_tf32(v.w);
        }
        // W tile: 32 k-rows x 128 n-cols = 1024 float4
        #pragma unroll
        for (int u4 = tid; u4 < 1024; u4 += 256) {
            int k = u4 >> 5, n4 = (u4 & 31) << 2;
            const float4 v = *(const float4*)(Wexp + (size_t)(kt + k)*N + n0 + n4);
            sm.m.Ws[k][n4+0] = to_tf32(v.x);
            sm.m.Ws[k][n4+1] = to_tf32(v.y);
            sm.m.Ws[k][n4+2] = to_tf32(v.z);
            sm.m.Ws[k][n4+3] = to_tf32(v.w);
        }
        __syncthreads();

        #pragma unroll
        for (int ks = 0; ks < 4; ks++) {
            const int k0 = ks * 8;
            unsigned a[4][4];
            #pragma unroll
            for (int mf = 0; mf < 4; mf++) {
                int rb = row_base + mf*16;
                a[mf][0] = __float_as_uint(sm.m.Xs[rb + (lane>>2)    ][k0 + (lane&3)    ]);
                a[mf][1] = __float_as_uint(sm.m.Xs[rb + (lane>>2) + 8][k0 + (lane&3)    ]);
                a[mf][2] = __float_as_uint(sm.m.Xs[rb + (lane>>2)    ][k0 + (lane&3) + 4]);
                a[mf][3] = __float_as_uint(sm.m.Xs[rb + (lane>>2) + 8][k0 + (lane&3) + 4]);
            }
            unsigned b[4][2];
            #pragma unroll
            for (int nf = 0; nf < 4; nf++) {
                int cb = col_base + nf*8 + (lane>>2);
                b[nf][0] = __float_as_uint(sm.m.Ws[k0 + (lane&3)    ][cb]);
                b[nf][1] = __float_as_uint(sm.m.Ws[k0 + (lane&3) + 4][cb]);
            }
            #pragma unroll
            for (int mf = 0; mf < 4; mf++)
                #pragma unroll
                for (int nf = 0; nf < 4; nf++)
                    mma_tf32(c[mf][nf], a[mf], b[nf]);
        }
        __syncthreads();
    }

    // ---- epilogue: out += Z @ B[adapter], masked store ----
    __syncthreads();   // mainloop smem reads done; union reuse is now safe
    for (int u = tid; u < 512; u += 256) {   // Zs: 128 x 16 floats = 512 float4
        int r = u >> 2, j4 = (u & 3) << 2;
        int gm = m0 + r;
        int p  = off + (gm < cnt ? gm : (cnt - 1));
        *(float4*)&sm.e.Zs[r][j4] = *(const float4*)(g_Z + (size_t)p*RR + j4);
    }
    for (int u = tid; u < 1024; u += 256) {  // Bs: 2 x 16 x 128 floats = 1024 float4
        int a = u >> 9, rem = u & 511;
        int j = rem >> 5, n4 = (rem & 31) << 2;
        *(float4*)&sm.e.Bs[a][j][n4] =
            *(const float4*)(Bbase + (((size_t)a*NE + e)*RR + j)*N + n0 + n4);
    }
    __syncthreads();

    #pragma unroll
    for (int mf = 0; mf < 4; mf++) {
        int rl0 = row_base + mf*16 + (lane >> 2);
        int rl1 = rl0 + 8;
        int a0r = s_adp[rl0], a1r = s_adp[rl1];
        float z0[16], z1[16];
        #pragma unroll
        for (int j = 0; j < RR; j++) { z0[j] = sm.e.Zs[rl0][j]; z1[j] = sm.e.Zs[rl1][j]; }
        bool v0 = (m0 + rl0) < cnt;
        bool v1 = (m0 + rl1) < cnt;
        float* o0 = Out + (size_t)(off + m0 + rl0)*N + n0;
        float* o1 = Out + (size_t)(off + m0 + rl1)*N + n0;
        #pragma unroll
        for (int nf = 0; nf < 4; nf++) {
            int cl = col_base + nf*8 + ((lane & 3) << 1);
            float v00 = c[mf][nf][0], v01 = c[mf][nf][1];
            float v10 = c[mf][nf][2], v11 = c[mf][nf][3];
            #pragma unroll
            for (int j = 0; j < RR; j++) {
                v00 += z0[j] * sm.e.Bs[a0r][j][cl];
                v01 += z0[j] * sm.e.Bs[a0r][j][cl+1];
                v10 += z1[j] * sm.e.Bs[a1r][j][cl];
                v11 += z1[j] * sm.e.Bs[a1r][j][cl+1];
            }
            if (v0) { o0[cl] = v00; o0[cl+1] = v01; }
            if (v1) { o1[cl] = v10; o1[cl+1] = v11; }
        }
    }
}

// ---------------- h = silu(gate) * up, in place into g_G ----------------
__global__ void silu_kernel() {
    size_t i = (size_t)blockIdx.x * blockDim.x + threadIdx.x;   // float4 index
    float4 g = ((const float4*)g_G)[i];
    float4 u = ((const float4*)g_U)[i];
    float4 r;
    r.x = u.x * g.x / (1.f + expf(-g.x));
    r.y = u.y * g.y / (1.f + expf(-g.y));
    r.z = u.z * g.z / (1.f + expf(-g.z));
    r.w = u.w * g.w / (1.f + expf(-g.w));
    ((float4*)g_G)[i] = r;
}

// ---------------- combine: out[t] = sum_k rw[t,k] * g_O[pos(t,k)] ----------------
__global__ void combine_kernel(const float* __restrict__ rw, float* __restrict__ out) {
    int t = blockIdx.x;
    __shared__ int   s_pos[TOPK];
    __shared__ float s_w[TOPK];
    if (threadIdx.x < TOPK) {
        s_pos[threadIdx.x] = g_pos[t*TOPK + threadIdx.x];
        s_w[threadIdx.x]   = rw[t*TOPK + threadIdx.x];
    }
    __syncthreads();
    for (int h = threadIdx.x * 4; h < HD; h += blockDim.x * 4) {
        float4 acc = make_float4(0.f, 0.f, 0.f, 0.f);
        #pragma unroll
        for (int k = 0; k < TOPK; k++) {
            const float4 v = *(const float4*)(g_O + (size_t)s_pos[k]*HD + h);
            float w = s_w[k];
            acc.x += w * v.x; acc.y += w * v.y; acc.z += w * v.z; acc.w += w * v.w;
        }
        *(float4*)(out + (size_t)t*HD + h) = acc;
    }
}

// ---------------- launch ----------------
extern "C" void kernel_launch(void* const* d_in, const int* in_sizes, int n_in,
                              void* d_out, int out_size) {
    const float* hidden = (const float*)d_in[0];
    const int*   sel    = (const int*)  d_in[1];
    const float* rw     = (const float*)d_in[2];
    const int*   adp    = (const int*)  d_in[3];
    const float* Wg     = (const float*)d_in[4];
    const float* Ag     = (const float*)d_in[5];
    const float* Bg     = (const float*)d_in[6];
    const float* Wu     = (const float*)d_in[7];
    const float* Au     = (const float*)d_in[8];
    const float* Bu     = (const float*)d_in[9];
    const float* Wd     = (const float*)d_in[10];
    const float* Ad     = (const float*)d_in[11];
    const float* Bd     = (const float*)d_in[12];
    float* out = (float*)d_out;

    routing_kernel<<<1, 1024>>>(sel, adp);

    dim3 zgrid(1, 288, 1);
    dim3 gugrid(ID/128, 288, 1);   // (8, 288)
    dim3 dgrid(HD/128, 288, 1);    // (16, 288)

    // gate
    z_kernel<<<zgrid, 256>>>(hidden, Ag, 0, HD);
    gemm_kernel<<<gugrid, 256>>>(hidden, Wg, Bg, 0, HD, ID);
    // up
    z_kernel<<<zgrid, 256>>>(hidden, Au, 1, HD);
    gemm_kernel<<<gugrid, 256>>>(hidden, Wu, Bu, 1, HD, ID);
    // h = silu(gate) * up
    silu_kernel<<<(TE*(size_t)ID/4 + 255)/256, 256>>>();
    // down
    z_kernel<<<zgrid, 256>>>(nullptr, Ad, 2, ID);
    gemm_kernel<<<dgrid, 256>>>(nullptr, Wd, Bd, 2, ID, HD);
    // weighted combine over top-k
    combine_kernel<<<NT, 256>>>(rw, out);
}

// round 3
// speedup vs baseline: 1.0066x; 1.0066x over previous
#include <cuda_runtime.h>
#include <math.h>

// ---------------- problem constants ----------------
#define NE   32          // experts
#define TOPK 8
#define HD   2048        // hidden
#define ID   1024        // intermediate
#define AMAX 2
#define RR   16          // lora rank
#define NT   4096        // tokens
#define TE   (NT*TOPK)   // expanded tokens = 32768
#define MAXTILES 320     // >= sum ceil(cnt_e/128) (bounded by 287)

// ---------------- device scratch (static, no allocs) ----------------
__device__ int   g_cnt[NE];
__device__ int   g_off[NE+1];
__device__ int   g_tok[TE];     // source token per sorted position
__device__ int   g_adp[TE];     // adapter per sorted position
__device__ int   g_pos[TE];     // sorted position of expanded index i
__device__ int   g_tile_e[MAXTILES];
__device__ int   g_tile_m[MAXTILES];
__device__ int   g_ntiles;
__device__ float g_Z[(size_t)TE*RR];
__device__ float g_G[(size_t)TE*ID];   // gate, then h after silu
__device__ float g_U[(size_t)TE*ID];   // up
__device__ float g_O[(size_t)TE*HD];   // down output (sorted order)

// ---------------- helpers ----------------
__device__ __forceinline__ float to_tf32(float x) {
    unsigned u;
    asm("cvt.rna.tf32.f32 %0, %1;" : "=r"(u) : "f"(x));
    return __uint_as_float(u);
}

__device__ __forceinline__ void mma_tf32(float* c, const unsigned* a, const unsigned* b) {
    asm volatile(
        "mma.sync.aligned.m16n8k8.row.col.f32.tf32.tf32.f32 "
        "{%0,%1,%2,%3}, {%4,%5,%6,%7}, {%8,%9}, {%0,%1,%2,%3};\n"
        : "+f"(c[0]), "+f"(c[1]), "+f"(c[2]), "+f"(c[3])
        : "r"(a[0]), "r"(a[1]), "r"(a[2]), "r"(a[3]),
          "r"(b[0]), "r"(b[1]));
}

// ---------------- routing: count, scan, scatter, tile list ----------------
__global__ void routing_kernel(const int* __restrict__ sel, const int* __restrict__ adp) {
    __shared__ int s_cnt[NE];
    __shared__ int s_cur[NE];
    const int tid = threadIdx.x;
    if (tid < NE) s_cnt[tid] = 0;
    __syncthreads();
    for (int i = tid; i < TE; i += blockDim.x)
        atomicAdd(&s_cnt[sel[i]], 1);
    __syncthreads();
    if (tid == 0) {
        int acc = 0, idx = 0;
        for (int e = 0; e < NE; e++) {
            int c = s_cnt[e];
            g_cnt[e] = c;
            g_off[e] = acc;
            s_cur[e] = acc;
            acc += c;
            int mt = (c + 127) >> 7;
            for (int i = 0; i < mt; i++) { g_tile_e[idx] = e; g_tile_m[idx] = i; idx++; }
        }
        g_off[NE] = acc;
        g_ntiles = idx;
    }
    __syncthreads();
    for (int i = tid; i < TE; i += blockDim.x) {
        int e = sel[i];
        int pos = atomicAdd(&s_cur[e], 1);
        int t = i >> 3;  // TOPK = 8
        g_tok[pos] = t;
        g_adp[pos] = adp[t];
        g_pos[i]   = pos;
    }
}

// ---------------- LoRA A projection: Z[p,0..15] = x_p @ A[a_p, e_p] ----------------
// proj: 0/1 -> X = hidden (gathered rows, K=HD), 2 -> X = g_G (h, direct rows, K=ID)
__global__ __launch_bounds__(256)
void z_kernel(const float* __restrict__ hidden,
              const float* __restrict__ Abase,
              int proj, int K)
{
    if ((int)blockIdx.y >= g_ntiles) return;
    const int e   = g_tile_e[blockIdx.y];
    const int m0  = g_tile_m[blockIdx.y] << 7;
    const int cnt = g_cnt[e];
    const int off = g_off[e];

    const int tid = threadIdx.x;
    const int r   = tid >> 1;          // 0..127
    const int jb  = (tid & 1) * 8;     // j half
    const int gm  = m0 + r;
    const bool valid = gm < cnt;
    const int p = off + (valid ? gm : (cnt - 1));

    const float* xrow = (proj < 2) ? (hidden + (size_t)g_tok[p] * HD)
                                   : (g_G + (size_t)p * ID);
    const int a = g_adp[p];

    float z[8] = {0.f,0.f,0.f,0.f,0.f,0.f,0.f,0.f};

    __shared__ float As[2][64][20];   // pad 20: 16B-aligned rows, low conflicts

    for (int kt = 0; kt < K; kt += 64) {
        // load both adapters' A tile: 2*64*16 floats = 512 float4
        for (int u = tid; u < 512; u += 256) {
            int aa = u >> 8, rem = u & 255;
            int kk = rem >> 2, j4 = (rem & 3) << 2;
            float4 v = *(const float4*)(Abase + (((size_t)aa*NE + e)*K + kt + kk)*RR + j4);
            *(float4*)&As[aa][kk][j4] = v;
        }
        __syncthreads();
        #pragma unroll 4
        for (int kk = 0; kk < 64; kk++) {
            float xv = __ldg(xrow + kt + kk);
            float4 za = *(const float4*)&As[a][kk][jb];
            float4 zb = *(const float4*)&As[a][kk][jb + 4];
            z[0] += xv * za.x; z[1] += xv * za.y; z[2] += xv * za.z; z[3] += xv * za.w;
            z[4] += xv * zb.x; z[5] += xv * zb.y; z[6] += xv * zb.z; z[7] += xv * zb.w;
        }
        __syncthreads();
    }
    if (valid) {
        #pragma unroll
        for (int jj = 0; jj < 8; jj++)
            g_Z[(size_t)p*RR + jb + jj] = z[jj];
    }
}

// ---------------- grouped GEMM (tf32 mma) + LoRA-B epilogue ----------------
struct SmemMain { float Xs[128][36]; float Ws[32][136]; };
struct SmemEpi  { float Zs[128][16]; float Bs[2][16][128]; };
union SmemU { SmemMain m; SmemEpi e; };

// proj: 0 gate (X=hidden gather, out=g_G), 1 up (out=g_U), 2 down (X=g_G, out=g_O)
__global__ __launch_bounds__(256)
void gemm_kernel(const float* __restrict__ hidden,
                 const float* __restrict__ Wbase,
                 const float* __restrict__ Bbase,
                 int proj, int K, int N)
{
    if ((int)blockIdx.y >= g_ntiles) return;
    const int e   = g_tile_e[blockIdx.y];
    const int m0  = g_tile_m[blockIdx.y] << 7;
    const int cnt = g_cnt[e];
    const int off = g_off[e];
    const int n0  = blockIdx.x * 128;

    const int tid  = threadIdx.x;
    const int lane = tid & 31;
    const int wid  = tid >> 5;
    const int row_base = (wid & 1) * 64;   // 2 warps in M, 64 rows each
    const int col_base = (wid >> 1) * 32;  // 4 warps in N, 32 cols each

    __shared__ SmemU sm;
    __shared__ int s_src[128];
    __shared__ int s_adp[128];

    const float* Xbase; int ldx; int gather; float* Out;
    if (proj == 0)      { Xbase = hidden; ldx = HD; gather = 1; Out = g_G; }
    else if (proj == 1) { Xbase = hidden; ldx = HD; gather = 1; Out = g_U; }
    else                { Xbase = g_G;    ldx = ID; gather = 0; Out = g_O; }

    for (int r = tid; r < 128; r += 256) {
        int gm = m0 + r;
        int p  = off + (gm < cnt ? gm : (cnt - 1));
        s_src[r] = gather ? g_tok[p] : p;
        s_adp[r] = g_adp[p];
    }

    float c[4][4][4];
    #pragma unroll
    for (int i = 0; i < 4; i++)
        #pragma unroll
        for (int j = 0; j < 4; j++)
            #pragma unroll
            for (int k = 0; k < 4; k++) c[i][j][k] = 0.f;

    const float* Wexp = Wbase + (size_t)e * K * N;

    __syncthreads();

    for (int kt = 0; kt < K; kt += 32) {
        // X tile: 128 rows x 32 cols = 1024 float4
        #pragma unroll
        for (int u4 = tid; u4 < 1024; u4 += 256) {
            int r = u4 >> 3, c4 = (u4 & 7) << 2;
            const float4 v = *(const float4*)(Xbase + (size_t)s_src[r]*ldx + kt + c4);
            sm.m.Xs[r][c4+0] = to_tf32(v.x);
            sm.m.Xs[r][c4+1] = to_tf32(v.y);
            sm.m.Xs[r][c4+2] = to_tf32(v.z);
            sm.m.Xs[r][c4+3] = to_tf32(v.w);
        }
        // W tile: 32 k-rows x 128 n-cols = 1024 float4
        #pragma unroll
        for (int u4 = tid; u4 < 1024; u4 += 256) {
            int k = u4 >> 5, n4 = (u4 & 31) << 2;
            const float4 v = *(const float4*)(Wexp + (size_t)(kt + k)*N + n0 + n4);
            sm.m.Ws[k][n4+0] = to_tf32(v.x);
            sm.m.Ws[k][n4+1] = to_tf32(v.y);
            sm.m.Ws[k][n4+2] = to_tf32(v.z);
            sm.m.Ws[k][n4+3] = to_tf32(v.w);
        }
        __syncthreads();

        #pragma unroll
        for (int ks = 0; ks < 4; ks++) {
            const int k0 = ks * 8;
            unsigned a[4][4];
            #pragma unroll
            for (int mf = 0; mf < 4; mf++) {
                int rb = row_base + mf*16;
                a[mf][0] = __float_as_uint(sm.m.Xs[rb + (lane>>2)    ][k0 + (lane&3)    ]);
                a[mf][1] = __float_as_uint(sm.m.Xs[rb + (lane>>2) + 8][k0 + (lane&3)    ]);
                a[mf][2] = __float_as_uint(sm.m.Xs[rb + (lane>>2)    ][k0 + (lane&3) + 4]);
                a[mf][3] = __float_as_uint(sm.m.Xs[rb + (lane>>2) + 8][k0 + (lane&3) + 4]);
            }
            unsigned b[4][2];
            #pragma unroll
            for (int nf = 0; nf < 4; nf++) {
                int cb = col_base + nf*8 + (lane>>2);
                b[nf][0] = __float_as_uint(sm.m.Ws[k0 + (lane&3)    ][cb]);
                b[nf][1] = __float_as_uint(sm.m.Ws[k0 + (lane&3) + 4][cb]);
            }
            #pragma unroll
            for (int mf = 0; mf < 4; mf++)
                #pragma unroll
                for (int nf = 0; nf < 4; nf++)
                    mma_tf32(c[mf][nf], a[mf], b[nf]);
        }
        __syncthreads();
    }

    // ---- epilogue: out += Z @ B[adapter], masked store ----
    __syncthreads();   // mainloop smem reads done; union reuse is now safe
    for (int u = tid; u < 512; u += 256) {   // Zs: 128 x 16 floats = 512 float4
        int r = u >> 2, j4 = (u & 3) << 2;
        int gm = m0 + r;
        int p  = off + (gm < cnt ? gm : (cnt - 1));
        *(float4*)&sm.e.Zs[r][j4] = *(const float4*)(g_Z + (size_t)p*RR + j4);
    }
    for (int u = tid; u < 1024; u += 256) {  // Bs: 2 x 16 x 128 floats = 1024 float4
        int a = u >> 9, rem = u & 511;
        int j = rem >> 5, n4 = (rem & 31) << 2;
        *(float4*)&sm.e.Bs[a][j][n4] =
            *(const float4*)(Bbase + (((size_t)a*NE + e)*RR + j)*N + n0 + n4);
    }
    __syncthreads();

    #pragma unroll
    for (int mf = 0; mf < 4; mf++) {
        int rl0 = row_base + mf*16 + (lane >> 2);
        int rl1 = rl0 + 8;
        int a0r = s_adp[rl0], a1r = s_adp[rl1];
        float z0[16], z1[16];
        #pragma unroll
        for (int j = 0; j < RR; j++) { z0[j] = sm.e.Zs[rl0][j]; z1[j] = sm.e.Zs[rl1][j]; }
        bool v0 = (m0 + rl0) < cnt;
        bool v1 = (m0 + rl1) < cnt;
        float* o0 = Out + (size_t)(off + m0 + rl0)*N + n0;
        float* o1 = Out + (size_t)(off + m0 + rl1)*N + n0;
        #pragma unroll
        for (int nf = 0; nf < 4; nf++) {
            int cl = col_base + nf*8 + ((lane & 3) << 1);
            float v00 = c[mf][nf][0], v01 = c[mf][nf][1];
            float v10 = c[mf][nf][2], v11 = c[mf][nf][3];
            #pragma unroll
            for (int j = 0; j < RR; j++) {
                v00 += z0[j] * sm.e.Bs[a0r][j][cl];
                v01 += z0[j] * sm.e.Bs[a0r][j][cl+1];
                v10 += z1[j] * sm.e.Bs[a1r][j][cl];
                v11 += z1[j] * sm.e.Bs[a1r][j][cl+1];
            }
            if (v0) { o0[cl] = v00; o0[cl+1] = v01; }
            if (v1) { o1[cl] = v10; o1[cl+1] = v11; }
        }
    }
}

// ---------------- h = silu(gate) * up, in place into g_G ----------------
__global__ void silu_kernel() {
    size_t i = (size_t)blockIdx.x * blockDim.x + threadIdx.x;   // float4 index
    float4 g = ((const float4*)g_G)[i];
    float4 u = ((const float4*)g_U)[i];
    float4 r;
    r.x = u.x * g.x / (1.f + expf(-g.x));
    r.y = u.y * g.y / (1.f + expf(-g.y));
    r.z = u.z * g.z / (1.f + expf(-g.z));
    r.w = u.w * g.w / (1.f + expf(-g.w));
    ((float4*)g_G)[i] = r;
}

// ---------------- combine: out[t] = sum_k rw[t,k] * g_O[pos(t,k)] ----------------
__global__ void combine_kernel(const float* __restrict__ rw, float* __restrict__ out) {
    int t = blockIdx.x;
    __shared__ int   s_pos[TOPK];
    __shared__ float s_w[TOPK];
    if (threadIdx.x < TOPK) {
        s_pos[threadIdx.x] = g_pos[t*TOPK + threadIdx.x];
        s_w[threadIdx.x]   = rw[t*TOPK + threadIdx.x];
    }
    __syncthreads();
    for (int h = threadIdx.x * 4; h < HD; h += blockDim.x * 4) {
        float4 acc = make_float4(0.f, 0.f, 0.f, 0.f);
        #pragma unroll
        for (int k = 0; k < TOPK; k++) {
            const float4 v = *(const float4*)(g_O + (size_t)s_pos[k]*HD + h);
            float w = s_w[k];
            acc.x += w * v.x; acc.y += w * v.y; acc.z += w * v.z; acc.w += w * v.w;
        }
        *(float4*)(out + (size_t)t*HD + h) = acc;
    }
}

// ---------------- launch ----------------
extern "C" void kernel_launch(void* const* d_in, const int* in_sizes, int n_in,
                              void* d_out, int out_size) {
    const float* hidden = (const float*)d_in[0];
    const int*   sel    = (const int*)  d_in[1];
    const float* rw     = (const float*)d_in[2];
    const int*   adp    = (const int*)  d_in[3];
    const float* Wg     = (const float*)d_in[4];
    const float* Ag     = (const float*)d_in[5];
    const float* Bg     = (const float*)d_in[6];
    const float* Wu     = (const float*)d_in[7];
    const float* Au     = (const float*)d_in[8];
    const float* Bu     = (const float*)d_in[9];
    const float* Wd     = (const float*)d_in[10];
    const float* Ad     = (const float*)d_in[11];
    const float* Bd     = (const float*)d_in[12];
    float* out = (float*)d_out;

    routing_kernel<<<1, 1024>>>(sel, adp);

    dim3 zgrid(1, 288, 1);
    dim3 gugrid(ID/128, 288, 1);   // (8, 288)
    dim3 dgrid(HD/128, 288, 1);    // (16, 288)

    // gate
    z_kernel<<<zgrid, 256>>>(hidden, Ag, 0, HD);
    gemm_kernel<<<gugrid, 256>>>(hidden, Wg, Bg, 0, HD, ID);
    // up
    z_kernel<<<zgrid, 256>>>(hidden, Au, 1, HD);
    gemm_kernel<<<gugrid, 256>>>(hidden, Wu, Bu, 1, HD, ID);
    // h = silu(gate) * up
    silu_kernel<<<(TE*(size_t)ID/4 + 255)/256, 256>>>();
    // down
    z_kernel<<<zgrid, 256>>>(nullptr, Ad, 2, ID);
    gemm_kernel<<<dgrid, 256>>>(nullptr, Wd, Bd, 2, ID, HD);
    // weighted combine over top-k
    combine_kernel<<<NT, 256>>>(rw, out);
}

// round 5
// speedup vs baseline: 2.5752x; 2.5583x over previous
#include <cuda_runtime.h>
#include <cstdint>
#include <math.h>

#define NE 32
#define TOPK 8
#define HD 2048
#define ID 1024
#define NT 4096
#define TE (NT*TOPK)
#define MAXT 160

__device__ int g_cnt[NE], g_off[NE];
__device__ int g_tok[TE], g_adp[TE], g_pos[TE];
__device__ int g_te[MAXT], g_tm[MAXT];
__device__ int g_nt;
__device__ float g_Zgu[(size_t)TE*64];
__device__ float g_Zd[(size_t)TE*32];
__device__ float g_G[(size_t)TE*ID];   // gate, then h=silu(g)*u
__device__ float g_O[(size_t)TE*HD];

__device__ __forceinline__ uint32_t smem_u32(const void* p) {
    uint32_t a;
    asm("{ .reg .u64 t; cvta.to.shared.u64 t, %1; cvt.u32.u64 %0, t; }" : "=r"(a) : "l"(p));
    return a;
}
__device__ __forceinline__ uint32_t tf32u(float x) {
    uint32_t u;
    asm("cvt.rna.tf32.f32 %0, %1;" : "=r"(u) : "f"(x));
    return u;
}
__device__ __forceinline__ void cpa16(uint32_t dst, const float* src) {
    asm volatile("cp.async.cg.shared.global [%0], [%1], 16;" :: "r"(dst), "l"(src) : "memory");
}
__device__ __forceinline__ void cpa_commit() {
    asm volatile("cp.async.commit_group;" ::: "memory");
}
__device__ __forceinline__ void cpa_wait1() {
    asm volatile("cp.async.wait_group 1;" ::: "memory");
}
__device__ __forceinline__ void mma8(float* c, const uint32_t* a, const uint32_t* b) {
    asm volatile(
        "mma.sync.aligned.m16n8k8.row.col.f32.tf32.tf32.f32 "
        "{%0,%1,%2,%3}, {%4,%5,%6,%7}, {%8,%9}, {%0,%1,%2,%3};\n"
        : "+f"(c[0]), "+f"(c[1]), "+f"(c[2]), "+f"(c[3])
        : "r"(a[0]), "r"(a[1]), "r"(a[2]), "r"(a[3]), "r"(b[0]), "r"(b[1]));
}

__global__ void routing_kernel(const int* __restrict__ sel, const int* __restrict__ adp) {
    __shared__ int s_cnt[NE], s_cur[NE];
    int tid = threadIdx.x;
    if (tid < NE) s_cnt[tid] = 0;
    __syncthreads();
    for (int i = tid; i < TE; i += blockDim.x) atomicAdd(&s_cnt[sel[i]], 1);
    __syncthreads();
    if (tid == 0) {
        int acc = 0, idx = 0;
        for (int e = 0; e < NE; e++) {
            int c = s_cnt[e];
            g_cnt[e] = c; g_off[e] = acc; s_cur[e] = acc; acc += c;
            for (int i = 0; i < (c + 255) >> 8; i++) { g_te[idx] = e; g_tm[idx] = i; idx++; }
        }
        g_nt = idx;
    }
    __syncthreads();
    for (int i = tid; i < TE; i += blockDim.x) {
        int e = sel[i];
        int pos = atomicAdd(&s_cur[e], 1);
        int t = i >> 3;
        g_tok[pos] = t; g_adp[pos] = adp[t]; g_pos[i] = pos;
    }
}

// Unified tensor-core grouped GEMM, M-tile = 256 rows, 512 threads.
// ZMODE=0: Out = X @ W0[e] (+ LoRA chunk: Zmasked @ [B_a0;B_a1]); fuse=1 -> silu-combine into Out.
// ZMODE=1: Out = adapter-masked Z; B cols built from lora-A mats W0 (n<32) / W1 (n>=32).
template<int N_, int MW, int NWRP, int MF, int NF, int ZMODE>
__global__ __launch_bounds__(512, 1)
void mm_kernel(const float* __restrict__ X, const float* __restrict__ W0,
               const float* __restrict__ W1, const float* __restrict__ LB,
               const float* __restrict__ ZB, float* __restrict__ Out,
               int K, int NW, int ldx, int gather, int zld, int zoff, int fuse)
{
    if ((int)blockIdx.y >= g_nt) return;
    const int e   = g_te[blockIdx.y];
    const int m0  = g_tm[blockIdx.y] << 8;
    const int cnt = g_cnt[e];
    const int off = g_off[e];
    const int n0  = blockIdx.x * N_;

    extern __shared__ char smem[];
    int* s_src = (int*)smem;
    const int XSZ = 256 * 36 * 4;             // bytes per X stage
    const int WSZ = 32 * (N_ + 8) * 4;        // bytes per W stage
    const int STG = XSZ + WSZ;
    char* stg0 = smem + 1024;
    const uint32_t sb = smem_u32(stg0);

    const int tid  = threadIdx.x;
    const int lane = tid & 31;
    const int wid  = tid >> 5;
    const int row_base = (wid % MW) * (256 / MW);
    const int col_base = (wid / MW) * (N_ / NWRP);

    if (tid < 256) {
        int p = off + min(m0 + tid, cnt - 1);
        s_src[tid] = gather ? g_tok[p] : p;
    }
    __syncthreads();

    const int KC = K >> 5;
    const int KT = KC + (ZMODE ? 0 : 1);

    auto issue = [&](int kc, int buf) {
        const int k0 = kc << 5;
        const bool lora = (kc == KC);
        const uint32_t xb = sb + buf * STG;
        const uint32_t wb = xb + XSZ;
        // X tile: 256 rows x 32 k, raw fp32
        #pragma unroll
        for (int u = tid; u < 2048; u += 512) {
            int r = u >> 3, c4 = u & 7;
            const float* src;
            if (!lora) {
                src = X + (size_t)s_src[r] * ldx + k0 + c4 * 4;
            } else {
                int p = off + min(m0 + r, cnt - 1);
                src = ZB + (size_t)p * zld + zoff + c4 * 4;
            }
            cpa16(xb + r * 144 + c4 * 16, src);
        }
        if (!ZMODE) {
            // W tile [32 k][N_ n] via cp.async
            #pragma unroll
            for (int u = tid; u < (N_ << 3); u += 512) {
                int k = u / (N_ >> 2);
                int n4 = (u % (N_ >> 2)) << 2;
                const float* src;
                if (!lora)
                    src = W0 + ((size_t)e * K + k0 + k) * NW + n0 + n4;
                else
                    src = LB + (((size_t)(k >> 4) * NE + e) * 16 + (k & 15)) * NW + n0 + n4;
                cpa16(wb + (k * (N_ + 8) + n4) * 4, src);
            }
        } else {
            // lora-A tile: element-wise LDG+STS (non-contiguous k in gmem)
            for (int u = tid; u < N_ * 32; u += 512) {
                int n = u & (N_ - 1);
                int k = u / N_;
                const float* mat = (n < 32) ? W0 : W1;
                int a = (n >> 4) & 1;
                float v = __ldg(mat + (((size_t)a * NE + e) * K + k0 + k) * 16 + (n & 15));
                *(float*)(smem + 1024 + buf * STG + XSZ + (k * (N_ + 8) + n) * 4) = v;
            }
        }
    };

    float c[MF][NF][4];
    #pragma unroll
    for (int i = 0; i < MF; i++)
        #pragma unroll
        for (int j = 0; j < NF; j++) { c[i][j][0]=0.f; c[i][j][1]=0.f; c[i][j][2]=0.f; c[i][j][3]=0.f; }

    issue(0, 0); cpa_commit();
    if (KT > 1) issue(1, 1);
    cpa_commit();

    for (int kc = 0; kc < KT; kc++) {
        cpa_wait1();
        __syncthreads();
        const int buf = kc & 1;
        const float* xs = (const float*)(smem + 1024 + buf * STG);
        const float* ws = (const float*)(smem + 1024 + buf * STG + XSZ);
        #pragma unroll
        for (int ks = 0; ks < 4; ks++) {
            const int k0 = ks * 8;
            uint32_t a[MF][4];
            #pragma unroll
            for (int mf = 0; mf < MF; mf++) {
                int r0 = row_base + mf * 16 + (lane >> 2);
                a[mf][0] = tf32u(xs[r0 * 36 + k0 + (lane & 3)]);
                a[mf][1] = tf32u(xs[(r0 + 8) * 36 + k0 + (lane & 3)]);
                a[mf][2] = tf32u(xs[r0 * 36 + k0 + (lane & 3) + 4]);
                a[mf][3] = tf32u(xs[(r0 + 8) * 36 + k0 + (lane & 3) + 4]);
            }
            uint32_t b[NF][2];
            #pragma unroll
            for (int nf = 0; nf < NF; nf++) {
                int cb = col_base + nf * 8 + (lane >> 2);
                b[nf][0] = tf32u(ws[(k0 + (lane & 3)) * (N_ + 8) + cb]);
                b[nf][1] = tf32u(ws[(k0 + (lane & 3) + 4) * (N_ + 8) + cb]);
            }
            #pragma unroll
            for (int mf = 0; mf < MF; mf++)
                #pragma unroll
                for (int nf = 0; nf < NF; nf++)
                    mma8(c[mf][nf], a[mf], b[nf]);
        }
        __syncthreads();
        if (kc + 2 < KT) issue(kc + 2, buf);
        cpa_commit();
    }

    // ---------------- epilogue ----------------
    #pragma unroll
    for (int mf = 0; mf < MF; mf++) {
        int rl0 = row_base + mf * 16 + (lane >> 2);
        int rl1 = rl0 + 8;
        bool v0 = (m0 + rl0) < cnt;
        bool v1 = (m0 + rl1) < cnt;
        int p0 = off + min(m0 + rl0, cnt - 1);
        int p1 = off + min(m0 + rl1, cnt - 1);
        if (ZMODE) {
            int a0 = g_adp[p0], a1 = g_adp[p1];
            #pragma unroll
            for (int nf = 0; nf < NF; nf++) {
                int cl = col_base + nf * 8 + ((lane & 3) << 1);
                #pragma unroll
                for (int q = 0; q < 2; q++) {
                    int col = cl + q;
                    int sla = (col & 31) >> 4;
                    if (v0) Out[(size_t)p0 * NW + col] = (sla == a0) ? c[mf][nf][q]     : 0.f;
                    if (v1) Out[(size_t)p1 * NW + col] = (sla == a1) ? c[mf][nf][2 + q] : 0.f;
                }
            }
        } else if (fuse) {
            #pragma unroll
            for (int nf = 0; nf < NF; nf++) {
                int cl = col_base + nf * 8 + ((lane & 3) << 1);
                #pragma unroll
                for (int q = 0; q < 2; q++) {
                    if (v0) {
                        size_t i = (size_t)p0 * NW + n0 + cl + q;
                        float g = Out[i];
                        Out[i] = c[mf][nf][q] * g / (1.f + expf(-g));
                    }
                    if (v1) {
                        size_t i = (size_t)p1 * NW + n0 + cl + q;
                        float g = Out[i];
                        Out[i] = c[mf][nf][2 + q] * g / (1.f + expf(-g));
                    }
                }
            }
        } else {
            #pragma unroll
            for (int nf = 0; nf < NF; nf++) {
                int cl = col_base + nf * 8 + ((lane & 3) << 1);
                float2 w0 = make_float2(c[mf][nf][0], c[mf][nf][1]);
                float2 w1 = make_float2(c[mf][nf][2], c[mf][nf][3]);
                if (v0) *(float2*)(Out + (size_t)p0 * NW + n0 + cl) = w0;
                if (v1) *(float2*)(Out + (size_t)p1 * NW + n0 + cl) = w1;
            }
        }
    }
}

__global__ void combine_kernel(const float* __restrict__ rw, float* __restrict__ out) {
    int t = blockIdx.x;
    __shared__ int s_pos[TOPK];
    __shared__ float s_w[TOPK];
    if (threadIdx.x < TOPK) {
        s_pos[threadIdx.x] = g_pos[t*TOPK + threadIdx.x];
        s_w[threadIdx.x]   = rw[t*TOPK + threadIdx.x];
    }
    __syncthreads();
    for (int h = threadIdx.x * 4; h < HD; h += blockDim.x * 4) {
        float4 acc = make_float4(0.f, 0.f, 0.f, 0.f);
        #pragma unroll
        for (int k = 0; k < TOPK; k++) {
            const float4 v = *(const float4*)(g_O + (size_t)s_pos[k]*HD + h);
            float w = s_w[k];
            acc.x += w*v.x; acc.y += w*v.y; acc.z += w*v.z; acc.w += w*v.w;
        }
        *(float4*)(out + (size_t)t*HD + h) = acc;
    }
}

#define SM_MAIN (1024 + 2*(256*36*4 + 32*136*4))
#define SM_Z64  (1024 + 2*(256*36*4 + 32*72*4))
#define SM_Z32  (1024 + 2*(256*36*4 + 32*40*4))

extern "C" void kernel_launch(void* const* d_in, const int* in_sizes, int n_in,
                              void* d_out, int out_size) {
    const float* hidden = (const float*)d_in[0];
    const int*   sel    = (const int*)  d_in[1];
    const float* rw     = (const float*)d_in[2];
    const int*   adp    = (const int*)  d_in[3];
    const float* Wg     = (const float*)d_in[4];
    const float* Ag     = (const float*)d_in[5];
    const float* Bg     = (const float*)d_in[6];
    const float* Wu     = (const float*)d_in[7];
    const float* Au     = (const float*)d_in[8];
    const float* Bu     = (const float*)d_in[9];
    const float* Wd     = (const float*)d_in[10];
    const float* Ad     = (const float*)d_in[11];
    const float* Bd     = (const float*)d_in[12];
    float* out = (float*)d_out;

    static bool init = false;
    if (!init) {
        cudaFuncSetAttribute(mm_kernel<128,4,4,4,4,0>, cudaFuncAttributeMaxDynamicSharedMemorySize, SM_MAIN);
        cudaFuncSetAttribute(mm_kernel<64,8,2,2,4,1>,  cudaFuncAttributeMaxDynamicSharedMemorySize, SM_Z64);
        cudaFuncSetAttribute(mm_kernel<32,16,1,1,4,1>, cudaFuncAttributeMaxDynamicSharedMemorySize, SM_Z32);
        init = true;
    }

    float *zgu, *zd, *G, *O;
    cudaGetSymbolAddress((void**)&zgu, g_Zgu);
    cudaGetSymbolAddress((void**)&zd,  g_Zd);
    cudaGetSymbolAddress((void**)&G,   g_G);
    cudaGetSymbolAddress((void**)&O,   g_O);

    routing_kernel<<<1, 1024>>>(sel, adp);

    // Z(gate|up, both adapters), adapter-masked: [TE][64]
    mm_kernel<64,8,2,2,4,1><<<dim3(1, MAXT), 512, SM_Z64>>>(
        hidden, Ag, Au, nullptr, nullptr, zgu, HD, 64, HD, 1, 0, 0, 0);
    // gate -> G
    mm_kernel<128,4,4,4,4,0><<<dim3(ID/128, MAXT), 512, SM_MAIN>>>(
        hidden, Wg, nullptr, Bg, zgu, G, HD, ID, HD, 1, 64, 0, 0);
    // up, fused: G = silu(G) * up
    mm_kernel<128,4,4,4,4,0><<<dim3(ID/128, MAXT), 512, SM_MAIN>>>(
        hidden, Wu, nullptr, Bu, zgu, G, HD, ID, HD, 1, 64, 32, 1);
    // Z(down), adapter-masked: [TE][32]
    mm_kernel<32,16,1,1,4,1><<<dim3(1, MAXT), 512, SM_Z32>>>(
        G, Ad, Ad, nullptr, nullptr, zd, ID, 32, ID, 0, 0, 0, 0);
    // down -> O
    mm_kernel<128,4,4,4,4,0><<<dim3(HD/128, MAXT), 512, SM_MAIN>>>(
        G, Wd, nullptr, Bd, zd, O, ID, HD, ID, 0, 32, 0, 0);

    combine_kernel<<<NT, 256>>>(rw, out);
}